// round 1
// baseline (speedup 1.0000x reference)
#include <cuda_runtime.h>
#include <cstdint>

#define EPS 1e-5f

// Problem dims
constexpr int T_   = 4;
constexpr int B_   = 16;
constexpr int C_   = 256;
constexpr int MED  = 512;
constexpr int HW   = 1024;   // 32*32
constexpr int IMGS = 64;     // T*B

constexpr size_t N_X  = (size_t)T_ * B_ * C_  * HW;  // 16,777,216
constexpr size_t N_Y1 = (size_t)T_ * B_ * MED * HW;  // 33,554,432
constexpr size_t STRIDE_T_C = (size_t)B_ * C_  * HW; // 4,194,304
constexpr size_t STRIDE_T_M = (size_t)B_ * MED * HW; // 8,388,608

// ---------------- scratch (device globals; no cudaMalloc allowed) ----------
__device__ unsigned char g_s1[N_X];     // stage1 spikes  [T,B,C,HW]
__device__ float         g_y1[N_Y1];    // stage1 output  [T,B,MED,HW]
__device__ unsigned char g_s3[N_Y1];    // stage3 spikes  [T,B,MED,HW]
__device__ float         g_zv[N_X];     // stage3 1x1 conv variable part [T,B,C,HW]

__device__ float g_W1f[MED * C_];       // w_pw1 * inv1(o)
__device__ float g_bias1[MED];          // b1 - m1*inv1
__device__ float g_W2f[C_ * MED];       // w_rep1 * invp(k)
__device__ float g_wdw2f[MED * 9];      // w_dw2 * inv2(c)
__device__ float g_c2[MED];             // b2 - m2*inv2
__device__ float g_cp[MED];             // bp - mp*invp
__device__ float g_wr2f[C_ * 9];        // w_rep2 * inv3(o)
__device__ float g_Bt[C_];              // total bias for final dw+BN3

// ---------------- prep kernels (fold BN into weights) ----------------------
__global__ void prep_small(const float* __restrict__ g1, const float* __restrict__ b1,
                           const float* __restrict__ m1, const float* __restrict__ v1,
                           const float* __restrict__ g2, const float* __restrict__ b2,
                           const float* __restrict__ m2, const float* __restrict__ v2,
                           const float* __restrict__ gp, const float* __restrict__ bp,
                           const float* __restrict__ mp, const float* __restrict__ vp,
                           const float* __restrict__ w_dw2)
{
    int i = threadIdx.x;  // 512
    float inv1 = g1[i] / sqrtf(v1[i] + EPS);
    g_bias1[i] = b1[i] - m1[i] * inv1;

    float inv2 = g2[i] / sqrtf(v2[i] + EPS);
    g_c2[i] = b2[i] - m2[i] * inv2;
#pragma unroll
    for (int j = 0; j < 9; j++) g_wdw2f[i * 9 + j] = w_dw2[i * 9 + j] * inv2;

    float invp = gp[i] / sqrtf(vp[i] + EPS);
    g_cp[i] = bp[i] - mp[i] * invp;
}

__global__ void prep_w1(const float* __restrict__ w_pw1,
                        const float* __restrict__ g1, const float* __restrict__ v1)
{
    int o = blockIdx.x;        // 512
    int k = threadIdx.x;       // 256
    float inv1 = g1[o] / sqrtf(v1[o] + EPS);
    g_W1f[o * C_ + k] = w_pw1[o * C_ + k] * inv1;
}

__global__ void prep_w2(const float* __restrict__ w_rep1,
                        const float* __restrict__ gp, const float* __restrict__ vp)
{
    int o = blockIdx.x;        // 256
    int k = threadIdx.x;       // 512
    float invp = gp[k] / sqrtf(vp[k] + EPS);
    g_W2f[o * MED + k] = w_rep1[o * MED + k] * invp;
}

__global__ void prep_rep(const float* __restrict__ w_rep1, const float* __restrict__ w_rep2,
                         const float* __restrict__ g3, const float* __restrict__ b3,
                         const float* __restrict__ m3, const float* __restrict__ v3)
{
    int o = threadIdx.x;       // 256
    float cb = 0.f;
    for (int k = 0; k < MED; k++) cb += w_rep1[o * MED + k] * g_cp[k];
    float inv3 = g3[o] / sqrtf(v3[o] + EPS);
    float sw = 0.f;
#pragma unroll
    for (int j = 0; j < 9; j++) {
        float wv = w_rep2[o * 9 + j];
        g_wr2f[o * 9 + j] = wv * inv3;
        sw += wv;
    }
    g_Bt[o] = (b3[o] - m3[o] * inv3) + inv3 * cb * sw;
}

// ---------------- stage 1 LIF -----------------------------------------------
__device__ __forceinline__ float quant01(float m) {
    return rintf(fminf(fmaxf(m, 0.f), 1.f));   // round-half-to-even, matches jnp.round
}

__global__ void lif1_kernel(const float* __restrict__ x)
{
    size_t idx = (size_t)blockIdx.x * blockDim.x + threadIdx.x;  // < STRIDE_T_C
    float mem = 0.f, sp = 0.f;
#pragma unroll
    for (int t = 0; t < T_; t++) {
        float v = x[(size_t)t * STRIDE_T_C + idx];
        mem = (mem - sp * 0.5f) * 0.25f + v;
        sp  = quant01(mem);
        g_s1[(size_t)t * STRIDE_T_C + idx] = (unsigned char)sp;
    }
}

// ---------------- spike GEMM: C[img] = A[M,K] * B[img][K,1024] (+bias) ------
#define BM 128
#define BN 128
#define BK 8

__device__ __forceinline__ void gemm_body(const float* __restrict__ A,
                                          const unsigned char* __restrict__ Bimg,
                                          float* __restrict__ Cimg,
                                          const float* __restrict__ bias,
                                          int M, int K, bool use_bias)
{
    int img = blockIdx.z;
    const unsigned char* Bp = Bimg + (size_t)img * K * HW;
    float* Cp = Cimg + (size_t)img * M * HW;
    int m0 = blockIdx.y * BM;
    int n0 = blockIdx.x * BN;

    __shared__ __align__(16) float As[BK][BM];
    __shared__ __align__(16) float Bs[BK][BN];

    int tid = threadIdx.x;               // 256
    int arow = tid >> 1, acol = (tid & 1) * 4;
    int brow = tid >> 5, bcol = (tid & 31) * 4;
    int ty = tid >> 4, tx = tid & 15;

    float acc[8][8];
#pragma unroll
    for (int i = 0; i < 8; i++)
#pragma unroll
        for (int j = 0; j < 8; j++) acc[i][j] = 0.f;

    for (int k0 = 0; k0 < K; k0 += BK) {
        float4 av = *(const float4*)(A + (size_t)(m0 + arow) * K + k0 + acol);
        As[acol + 0][arow] = av.x;
        As[acol + 1][arow] = av.y;
        As[acol + 2][arow] = av.z;
        As[acol + 3][arow] = av.w;

        uchar4 bv = *(const uchar4*)(Bp + (size_t)(k0 + brow) * HW + n0 + bcol);
        Bs[brow][bcol + 0] = (float)bv.x;
        Bs[brow][bcol + 1] = (float)bv.y;
        Bs[brow][bcol + 2] = (float)bv.z;
        Bs[brow][bcol + 3] = (float)bv.w;

        __syncthreads();
#pragma unroll
        for (int kk = 0; kk < BK; ++kk) {
            float4 t0 = *(const float4*)&As[kk][ty * 4];
            float4 t1 = *(const float4*)&As[kk][64 + ty * 4];
            float4 t2 = *(const float4*)&Bs[kk][tx * 4];
            float4 t3 = *(const float4*)&Bs[kk][64 + tx * 4];
            float a[8] = {t0.x, t0.y, t0.z, t0.w, t1.x, t1.y, t1.z, t1.w};
            float b[8] = {t2.x, t2.y, t2.z, t2.w, t3.x, t3.y, t3.z, t3.w};
#pragma unroll
            for (int i = 0; i < 8; i++)
#pragma unroll
                for (int j = 0; j < 8; j++)
                    acc[i][j] = fmaf(a[i], b[j], acc[i][j]);
        }
        __syncthreads();
    }

#pragma unroll
    for (int i = 0; i < 8; i++) {
        int gr = m0 + ((i < 4) ? (ty * 4 + i) : (64 + ty * 4 + i - 4));
        float bb = use_bias ? bias[gr] : 0.f;
        float4 v0 = make_float4(acc[i][0] + bb, acc[i][1] + bb, acc[i][2] + bb, acc[i][3] + bb);
        float4 v1 = make_float4(acc[i][4] + bb, acc[i][5] + bb, acc[i][6] + bb, acc[i][7] + bb);
        *(float4*)(Cp + (size_t)gr * HW + n0 + tx * 4)      = v0;
        *(float4*)(Cp + (size_t)gr * HW + n0 + 64 + tx * 4) = v1;
    }
}

__global__ void __launch_bounds__(256) gemm1_kernel()
{
    gemm_body(g_W1f, g_s1, g_y1, g_bias1, MED, C_, true);
}

__global__ void __launch_bounds__(256) gemm2_kernel()
{
    gemm_body(g_W2f, g_s3, g_zv, nullptr, C_, MED, false);
}

// ---------------- fused LIF2 + dw3x3+BN2 + LIF3 ----------------------------
// One block per (b, c) channel plane; smem spike tile persists across T.
__global__ void __launch_bounds__(256) mid_kernel()
{
    int bx = blockIdx.x;          // 16*512
    int b  = bx >> 9;
    int c  = bx & 511;
    size_t chanbase = ((size_t)b * MED + c) * HW;

    __shared__ float tile[HW];

    float wreg[9];
#pragma unroll
    for (int j = 0; j < 9; j++) wreg[j] = g_wdw2f[c * 9 + j];
    float cc = g_c2[c];

    int tid = threadIdx.x;        // 256, each thread owns 4 pixels strided
    float mem2[4] = {0, 0, 0, 0}, sp2[4] = {0, 0, 0, 0};
    float mem3[4] = {0, 0, 0, 0}, sp3[4] = {0, 0, 0, 0};

#pragma unroll
    for (int t = 0; t < T_; t++) {
        size_t base = (size_t)t * STRIDE_T_M + chanbase;
#pragma unroll
        for (int i = 0; i < 4; i++) {
            int p = tid + i * 256;
            float v = g_y1[base + p];
            mem2[i] = (mem2[i] - sp2[i] * 0.5f) * 0.25f + v;
            sp2[i]  = quant01(mem2[i]);
            tile[p] = sp2[i];
        }
        __syncthreads();
#pragma unroll
        for (int i = 0; i < 4; i++) {
            int p = tid + i * 256;
            int h = p >> 5, wcol = p & 31;
            float conv = 0.f;
#pragma unroll
            for (int ky = 0; ky < 3; ky++) {
                int hh = h + ky - 1;
                if ((unsigned)hh < 32u) {
#pragma unroll
                    for (int kx = 0; kx < 3; kx++) {
                        int ww = wcol + kx - 1;
                        if ((unsigned)ww < 32u)
                            conv = fmaf(wreg[ky * 3 + kx], tile[hh * 32 + ww], conv);
                    }
                }
            }
            float y2v = conv + cc;
            mem3[i] = (mem3[i] - sp3[i] * 0.5f) * 0.25f + y2v;
            sp3[i]  = quant01(mem3[i]);
            g_s3[base + p] = (unsigned char)sp3[i];
        }
        __syncthreads();
    }
}

// ---------------- final dw3x3 (+folded BN3 + pad-ring bias) ----------------
__global__ void __launch_bounds__(256) dw3_kernel(float* __restrict__ out)
{
    int plane = blockIdx.x;        // 64*256
    int o = plane & 255;
    size_t base = (size_t)plane * HW;

    __shared__ float tile[HW];

    float wreg[9];
#pragma unroll
    for (int j = 0; j < 9; j++) wreg[j] = g_wr2f[o * 9 + j];
    float bt = g_Bt[o];

    int tid = threadIdx.x;
#pragma unroll
    for (int i = 0; i < 4; i++) {
        int p = tid + i * 256;
        tile[p] = g_zv[base + p];
    }
    __syncthreads();
#pragma unroll
    for (int i = 0; i < 4; i++) {
        int p = tid + i * 256;
        int h = p >> 5, wcol = p & 31;
        float conv = 0.f;
#pragma unroll
        for (int ky = 0; ky < 3; ky++) {
            int hh = h + ky - 1;
            if ((unsigned)hh < 32u) {
#pragma unroll
                for (int kx = 0; kx < 3; kx++) {
                    int ww = wcol + kx - 1;
                    if ((unsigned)ww < 32u)
                        conv = fmaf(wreg[ky * 3 + kx], tile[hh * 32 + ww], conv);
                }
            }
        }
        out[base + p] = conv + bt;
    }
}

// ---------------- launch ---------------------------------------------------
extern "C" void kernel_launch(void* const* d_in, const int* in_sizes, int n_in,
                              void* d_out, int out_size)
{
    const float* x      = (const float*)d_in[0];
    const float* w_pw1  = (const float*)d_in[1];
    const float* g1 = (const float*)d_in[2];
    const float* b1 = (const float*)d_in[3];
    const float* m1 = (const float*)d_in[4];
    const float* v1 = (const float*)d_in[5];
    const float* w_dw2  = (const float*)d_in[6];
    const float* g2 = (const float*)d_in[7];
    const float* b2 = (const float*)d_in[8];
    const float* m2 = (const float*)d_in[9];
    const float* v2 = (const float*)d_in[10];
    const float* gp = (const float*)d_in[11];
    const float* bp = (const float*)d_in[12];
    const float* mp = (const float*)d_in[13];
    const float* vp = (const float*)d_in[14];
    const float* w_rep1 = (const float*)d_in[15];
    const float* w_rep2 = (const float*)d_in[16];
    const float* g3 = (const float*)d_in[17];
    const float* b3 = (const float*)d_in[18];
    const float* m3 = (const float*)d_in[19];
    const float* v3 = (const float*)d_in[20];
    float* out = (float*)d_out;

    prep_small<<<1, 512>>>(g1, b1, m1, v1, g2, b2, m2, v2, gp, bp, mp, vp, w_dw2);
    prep_w1<<<MED, C_>>>(w_pw1, g1, v1);
    prep_w2<<<C_, MED>>>(w_rep1, gp, vp);
    prep_rep<<<1, C_>>>(w_rep1, w_rep2, g3, b3, m3, v3);

    lif1_kernel<<<(int)(STRIDE_T_C / 256), 256>>>(x);

    gemm1_kernel<<<dim3(HW / BN, MED / BM, IMGS), 256>>>();   // (8,4,64)

    mid_kernel<<<B_ * MED, 256>>>();                          // 8192 blocks

    gemm2_kernel<<<dim3(HW / BN, C_ / BM, IMGS), 256>>>();    // (8,2,64)

    dw3_kernel<<<IMGS * C_, 256>>>(out);                      // 16384 blocks
}

// round 4
// speedup vs baseline: 1.5457x; 1.5457x over previous
#include <cuda_runtime.h>
#include <cuda_bf16.h>
#include <cstdint>

#define EPS 1e-5f

// Problem dims
constexpr int T_   = 4;
constexpr int B_   = 16;
constexpr int C_   = 256;
constexpr int MED  = 512;
constexpr int HW   = 1024;   // 32*32
constexpr int IMGS = 64;     // T*B

constexpr size_t N_X  = (size_t)T_ * B_ * C_  * HW;  // 16,777,216
constexpr size_t N_Y1 = (size_t)T_ * B_ * MED * HW;  // 33,554,432
constexpr size_t STRIDE_T_C = (size_t)B_ * C_  * HW;
constexpr size_t STRIDE_T_M = (size_t)B_ * MED * HW;

// ---------------- scratch (device globals) ---------------------------------
__device__ unsigned char g_s1[N_X];     // stage1 spikes  [T,B,C,HW]
__device__ float         g_y1[N_Y1];    // stage1 output  [T,B,MED,HW]
__device__ unsigned char g_s3[N_Y1];    // stage3 spikes  [T,B,MED,HW]
__device__ float         g_zv[N_X];     // stage3 1x1 conv variable part

__device__ __nv_bfloat16 g_W1hi[MED * C_];
__device__ __nv_bfloat16 g_W1md[MED * C_];
__device__ __nv_bfloat16 g_W1lo[MED * C_];
__device__ __nv_bfloat16 g_W2hi[C_ * MED];
__device__ __nv_bfloat16 g_W2md[C_ * MED];
__device__ __nv_bfloat16 g_W2lo[C_ * MED];
__device__ float g_bias1[MED];          // b1 - m1*inv1
__device__ float g_wdw2f[MED * 9];      // w_dw2 * inv2(c)
__device__ float g_c2[MED];             // b2 - m2*inv2
__device__ float g_cp[MED];             // bp - mp*invp
__device__ float g_wr2f[C_ * 9];        // w_rep2 * inv3(o)
__device__ float g_Bt[C_];              // total bias for final dw+BN3

// ---------------- prep kernels ---------------------------------------------
__global__ void prep_small(const float* __restrict__ g1, const float* __restrict__ b1,
                           const float* __restrict__ m1, const float* __restrict__ v1,
                           const float* __restrict__ g2, const float* __restrict__ b2,
                           const float* __restrict__ m2, const float* __restrict__ v2,
                           const float* __restrict__ gp, const float* __restrict__ bp,
                           const float* __restrict__ mp, const float* __restrict__ vp,
                           const float* __restrict__ w_dw2)
{
    int i = threadIdx.x;  // 512
    float inv1 = g1[i] / sqrtf(v1[i] + EPS);
    g_bias1[i] = b1[i] - m1[i] * inv1;

    float inv2 = g2[i] / sqrtf(v2[i] + EPS);
    g_c2[i] = b2[i] - m2[i] * inv2;
#pragma unroll
    for (int j = 0; j < 9; j++) g_wdw2f[i * 9 + j] = w_dw2[i * 9 + j] * inv2;

    float invp = gp[i] / sqrtf(vp[i] + EPS);
    g_cp[i] = bp[i] - mp[i] * invp;
}

__device__ __forceinline__ void split3(float w, __nv_bfloat16& hi, __nv_bfloat16& md,
                                       __nv_bfloat16& lo)
{
    hi = __float2bfloat16(w);
    float r1 = w - __bfloat162float(hi);
    md = __float2bfloat16(r1);
    float r2 = r1 - __bfloat162float(md);
    lo = __float2bfloat16(r2);
}

__global__ void prep_w1(const float* __restrict__ w_pw1,
                        const float* __restrict__ g1, const float* __restrict__ v1)
{
    int o = blockIdx.x;        // 512
    int k = threadIdx.x;       // 256
    float inv1 = g1[o] / sqrtf(v1[o] + EPS);
    float w = w_pw1[o * C_ + k] * inv1;
    __nv_bfloat16 hi, md, lo;
    split3(w, hi, md, lo);
    g_W1hi[o * C_ + k] = hi;
    g_W1md[o * C_ + k] = md;
    g_W1lo[o * C_ + k] = lo;
}

__global__ void prep_w2(const float* __restrict__ w_rep1,
                        const float* __restrict__ gp, const float* __restrict__ vp)
{
    int o = blockIdx.x;        // 256
    int k = threadIdx.x;       // 512
    float invp = gp[k] / sqrtf(vp[k] + EPS);
    float w = w_rep1[o * MED + k] * invp;
    __nv_bfloat16 hi, md, lo;
    split3(w, hi, md, lo);
    g_W2hi[o * MED + k] = hi;
    g_W2md[o * MED + k] = md;
    g_W2lo[o * MED + k] = lo;
}

// One block per output channel o; parallel reduction over k.
__global__ void prep_rep(const float* __restrict__ w_rep1, const float* __restrict__ w_rep2,
                         const float* __restrict__ g3, const float* __restrict__ b3,
                         const float* __restrict__ m3, const float* __restrict__ v3)
{
    int o = blockIdx.x;        // 256
    int tid = threadIdx.x;     // 256
    float p = w_rep1[o * MED + tid] * g_cp[tid]
            + w_rep1[o * MED + 256 + tid] * g_cp[256 + tid];
    __shared__ float red[256];
    red[tid] = p;
    __syncthreads();
    for (int s = 128; s > 0; s >>= 1) {
        if (tid < s) red[tid] += red[tid + s];
        __syncthreads();
    }
    if (tid == 0) {
        float cb = red[0];
        float inv3 = g3[o] / sqrtf(v3[o] + EPS);
        float sw = 0.f;
#pragma unroll
        for (int j = 0; j < 9; j++) {
            float wv = w_rep2[o * 9 + j];
            g_wr2f[o * 9 + j] = wv * inv3;
            sw += wv;
        }
        g_Bt[o] = (b3[o] - m3[o] * inv3) + inv3 * cb * sw;
    }
}

// ---------------- stage 1 LIF -----------------------------------------------
__device__ __forceinline__ float quant01(float m) {
    return rintf(fminf(fmaxf(m, 0.f), 1.f));
}

__global__ void lif1_kernel(const float* __restrict__ x)
{
    size_t idx = (size_t)blockIdx.x * blockDim.x + threadIdx.x;
    float mem = 0.f, sp = 0.f;
#pragma unroll
    for (int t = 0; t < T_; t++) {
        float v = x[(size_t)t * STRIDE_T_C + idx];
        mem = (mem - sp * 0.5f) * 0.25f + v;
        sp  = quant01(mem);
        g_s1[(size_t)t * STRIDE_T_C + idx] = (unsigned char)sp;
    }
}

// ---------------- bf16 tensor-core spike GEMM (3-way split, dual acc) -------
// C[img][M,1024] = (Ahi + (Amd+Alo))[M,K] * spikes[img][K,1024] (+bias)
// hi pass -> accA ; md+lo passes -> accB (own scale, no truncation bias).
// Block tile 128x128x32, 8 warps in 2(m)x4(n), warp tile 64x32.

#define LDA_PAD 40   // 32 + 8 bf16 pad -> conflict-free ldmatrix
#define LDB_PAD 136  // 128 + 8

__device__ __forceinline__ void ldmx4(uint32_t& r0, uint32_t& r1, uint32_t& r2, uint32_t& r3,
                                      const __nv_bfloat16* p)
{
    uint32_t a = (uint32_t)__cvta_generic_to_shared(p);
    asm volatile("ldmatrix.sync.aligned.m8n8.x4.shared.b16 {%0,%1,%2,%3}, [%4];"
                 : "=r"(r0), "=r"(r1), "=r"(r2), "=r"(r3) : "r"(a));
}

__device__ __forceinline__ void ldmx2t(uint32_t& r0, uint32_t& r1, const __nv_bfloat16* p)
{
    uint32_t a = (uint32_t)__cvta_generic_to_shared(p);
    asm volatile("ldmatrix.sync.aligned.m8n8.x2.trans.shared.b16 {%0,%1}, [%2];"
                 : "=r"(r0), "=r"(r1) : "r"(a));
}

__device__ __forceinline__ void mma16816(float* c, uint32_t a0, uint32_t a1, uint32_t a2,
                                         uint32_t a3, uint32_t b0, uint32_t b1)
{
    asm volatile(
        "mma.sync.aligned.m16n8k16.row.col.f32.bf16.bf16.f32 "
        "{%0,%1,%2,%3}, {%4,%5,%6,%7}, {%8,%9}, {%0,%1,%2,%3};"
        : "+f"(c[0]), "+f"(c[1]), "+f"(c[2]), "+f"(c[3])
        : "r"(a0), "r"(a1), "r"(a2), "r"(a3), "r"(b0), "r"(b1));
}

template <int M, int K, bool BIAS>
__device__ __forceinline__ void gemm_tc_body(const __nv_bfloat16* __restrict__ Ahi,
                                             const __nv_bfloat16* __restrict__ Amd,
                                             const __nv_bfloat16* __restrict__ Alo,
                                             const unsigned char* __restrict__ Bspk,
                                             float* __restrict__ Cout,
                                             const float* __restrict__ bias)
{
    int img = blockIdx.z;
    const unsigned char* Bp = Bspk + (size_t)img * K * HW;
    float* Cp = Cout + (size_t)img * M * HW;
    int m0 = blockIdx.y * 128;
    int n0 = blockIdx.x * 128;

    __shared__ __align__(16) __nv_bfloat16 Ahs[128 * LDA_PAD];
    __shared__ __align__(16) __nv_bfloat16 Ams[128 * LDA_PAD];
    __shared__ __align__(16) __nv_bfloat16 Als[128 * LDA_PAD];
    __shared__ __align__(16) __nv_bfloat16 Bs[32 * LDB_PAD];

    int tid  = threadIdx.x;
    int warp = tid >> 5, lane = tid & 31;
    int warp_m = (warp & 1) * 64;   // 2 warps along M
    int warp_n = (warp >> 1) * 32;  // 4 warps along N

    float accA[4][4][4];   // hi pass
    float accB[4][4][4];   // md + lo passes (magnitude ~2^-9)
#pragma unroll
    for (int i = 0; i < 4; i++)
#pragma unroll
        for (int j = 0; j < 4; j++)
#pragma unroll
            for (int q = 0; q < 4; q++) { accA[i][j][q] = 0.f; accB[i][j][q] = 0.f; }

    int arow = tid >> 1;              // 0..127
    int acol = (tid & 1) * 16;
    int brow = tid >> 3;              // 0..31
    int bcol = (tid & 7) * 16;

    for (int kc = 0; kc < K; kc += 32) {
        // ---- A hi/md/lo: 128 x 32 bf16 each ----
        {
            const uint4* s0 = (const uint4*)(Ahi + (size_t)(m0 + arow) * K + kc + acol);
            uint4 v0 = s0[0], v1 = s0[1];
            *(uint4*)&Ahs[arow * LDA_PAD + acol]     = v0;
            *(uint4*)&Ahs[arow * LDA_PAD + acol + 8] = v1;
            const uint4* s1 = (const uint4*)(Amd + (size_t)(m0 + arow) * K + kc + acol);
            uint4 u0 = s1[0], u1 = s1[1];
            *(uint4*)&Ams[arow * LDA_PAD + acol]     = u0;
            *(uint4*)&Ams[arow * LDA_PAD + acol + 8] = u1;
            const uint4* s2 = (const uint4*)(Alo + (size_t)(m0 + arow) * K + kc + acol);
            uint4 w0 = s2[0], w1 = s2[1];
            *(uint4*)&Als[arow * LDA_PAD + acol]     = w0;
            *(uint4*)&Als[arow * LDA_PAD + acol + 8] = w1;
        }
        // ---- B: 32 x 128 uint8 -> bf16 ----
        {
            uint4 raw = *(const uint4*)(Bp + (size_t)(kc + brow) * HW + n0 + bcol);
            uint32_t out[8];
            uint32_t ws[4] = {raw.x, raw.y, raw.z, raw.w};
#pragma unroll
            for (int q = 0; q < 4; q++) {
                uint32_t w = ws[q];
                out[q * 2 + 0] = ((w)       & 1u) * 0x3F80u | ((w >> 8)  & 1u) * 0x3F800000u;
                out[q * 2 + 1] = ((w >> 16) & 1u) * 0x3F80u | ((w >> 24) & 1u) * 0x3F800000u;
            }
            uint4* dst = (uint4*)&Bs[brow * LDB_PAD + bcol];
            dst[0] = make_uint4(out[0], out[1], out[2], out[3]);
            dst[1] = make_uint4(out[4], out[5], out[6], out[7]);
        }
        __syncthreads();

#pragma unroll
        for (int ks = 0; ks < 2; ks++) {
            int koff = ks * 16;
            uint32_t bf[4][2];
#pragma unroll
            for (int ni = 0; ni < 4; ni++) {
                const __nv_bfloat16* p = &Bs[(koff + (lane & 15)) * LDB_PAD + warp_n + ni * 8];
                ldmx2t(bf[ni][0], bf[ni][1], p);
            }
#pragma unroll
            for (int mi = 0; mi < 4; mi++) {
                int row = warp_m + mi * 16 + (lane & 15);
                int col = koff + (lane >> 4) * 8;
                uint32_t a0, a1, a2, a3;
                ldmx4(a0, a1, a2, a3, &Ahs[row * LDA_PAD + col]);
#pragma unroll
                for (int ni = 0; ni < 4; ni++)
                    mma16816(accA[mi][ni], a0, a1, a2, a3, bf[ni][0], bf[ni][1]);
                ldmx4(a0, a1, a2, a3, &Ams[row * LDA_PAD + col]);
#pragma unroll
                for (int ni = 0; ni < 4; ni++)
                    mma16816(accB[mi][ni], a0, a1, a2, a3, bf[ni][0], bf[ni][1]);
                ldmx4(a0, a1, a2, a3, &Als[row * LDA_PAD + col]);
#pragma unroll
                for (int ni = 0; ni < 4; ni++)
                    mma16816(accB[mi][ni], a0, a1, a2, a3, bf[ni][0], bf[ni][1]);
            }
        }
        __syncthreads();
    }

    // ---- epilogue: IEEE fp32 combine ----
#pragma unroll
    for (int mi = 0; mi < 4; mi++) {
        int r0 = m0 + warp_m + mi * 16 + (lane >> 2);
        int r1 = r0 + 8;
        float b0 = BIAS ? bias[r0] : 0.f;
        float b1 = BIAS ? bias[r1] : 0.f;
#pragma unroll
        for (int ni = 0; ni < 4; ni++) {
            int c = n0 + warp_n + ni * 8 + (lane & 3) * 2;
            float2 v0 = make_float2((accA[mi][ni][0] + accB[mi][ni][0]) + b0,
                                    (accA[mi][ni][1] + accB[mi][ni][1]) + b0);
            float2 v1 = make_float2((accA[mi][ni][2] + accB[mi][ni][2]) + b1,
                                    (accA[mi][ni][3] + accB[mi][ni][3]) + b1);
            *(float2*)(Cp + (size_t)r0 * HW + c) = v0;
            *(float2*)(Cp + (size_t)r1 * HW + c) = v1;
        }
    }
}

__global__ void __launch_bounds__(256) gemm1_kernel()
{
    gemm_tc_body<MED, C_, true>(g_W1hi, g_W1md, g_W1lo, g_s1, g_y1, g_bias1);
}

__global__ void __launch_bounds__(256) gemm2_kernel()
{
    gemm_tc_body<C_, MED, false>(g_W2hi, g_W2md, g_W2lo, g_s3, g_zv, nullptr);
}

// ---------------- fused LIF2 + dw3x3+BN2 + LIF3 ----------------------------
__global__ void __launch_bounds__(256) mid_kernel()
{
    int bx = blockIdx.x;          // 16*512
    int b  = bx >> 9;
    int c  = bx & 511;
    size_t chanbase = ((size_t)b * MED + c) * HW;

    __shared__ float tile[HW];

    float wreg[9];
#pragma unroll
    for (int j = 0; j < 9; j++) wreg[j] = g_wdw2f[c * 9 + j];
    float cc = g_c2[c];

    int tid = threadIdx.x;
    float mem2[4] = {0, 0, 0, 0}, sp2[4] = {0, 0, 0, 0};
    float mem3[4] = {0, 0, 0, 0}, sp3[4] = {0, 0, 0, 0};

#pragma unroll
    for (int t = 0; t < T_; t++) {
        size_t base = (size_t)t * STRIDE_T_M + chanbase;
#pragma unroll
        for (int i = 0; i < 4; i++) {
            int p = tid + i * 256;
            float v = g_y1[base + p];
            mem2[i] = (mem2[i] - sp2[i] * 0.5f) * 0.25f + v;
            sp2[i]  = quant01(mem2[i]);
            tile[p] = sp2[i];
        }
        __syncthreads();
#pragma unroll
        for (int i = 0; i < 4; i++) {
            int p = tid + i * 256;
            int h = p >> 5, wcol = p & 31;
            float conv = 0.f;
#pragma unroll
            for (int ky = 0; ky < 3; ky++) {
                int hh = h + ky - 1;
                if ((unsigned)hh < 32u) {
#pragma unroll
                    for (int kx = 0; kx < 3; kx++) {
                        int ww = wcol + kx - 1;
                        if ((unsigned)ww < 32u)
                            conv = fmaf(wreg[ky * 3 + kx], tile[hh * 32 + ww], conv);
                    }
                }
            }
            float y2v = conv + cc;
            mem3[i] = (mem3[i] - sp3[i] * 0.5f) * 0.25f + y2v;
            sp3[i]  = quant01(mem3[i]);
            g_s3[base + p] = (unsigned char)sp3[i];
        }
        __syncthreads();
    }
}

// ---------------- final dw3x3 (+folded BN3 + pad-ring bias) ----------------
__global__ void __launch_bounds__(256) dw3_kernel(float* __restrict__ out)
{
    int plane = blockIdx.x;        // 64*256
    int o = plane & 255;
    size_t base = (size_t)plane * HW;

    __shared__ float tile[HW];

    float wreg[9];
#pragma unroll
    for (int j = 0; j < 9; j++) wreg[j] = g_wr2f[o * 9 + j];
    float bt = g_Bt[o];

    int tid = threadIdx.x;
#pragma unroll
    for (int i = 0; i < 4; i++) {
        int p = tid + i * 256;
        tile[p] = g_zv[base + p];
    }
    __syncthreads();
#pragma unroll
    for (int i = 0; i < 4; i++) {
        int p = tid + i * 256;
        int h = p >> 5, wcol = p & 31;
        float conv = 0.f;
#pragma unroll
        for (int ky = 0; ky < 3; ky++) {
            int hh = h + ky - 1;
            if ((unsigned)hh < 32u) {
#pragma unroll
                for (int kx = 0; kx < 3; kx++) {
                    int ww = wcol + kx - 1;
                    if ((unsigned)ww < 32u)
                        conv = fmaf(wreg[ky * 3 + kx], tile[hh * 32 + ww], conv);
                }
            }
        }
        out[base + p] = conv + bt;
    }
}

// ---------------- launch ---------------------------------------------------
extern "C" void kernel_launch(void* const* d_in, const int* in_sizes, int n_in,
                              void* d_out, int out_size)
{
    const float* x      = (const float*)d_in[0];
    const float* w_pw1  = (const float*)d_in[1];
    const float* g1 = (const float*)d_in[2];
    const float* b1 = (const float*)d_in[3];
    const float* m1 = (const float*)d_in[4];
    const float* v1 = (const float*)d_in[5];
    const float* w_dw2  = (const float*)d_in[6];
    const float* g2 = (const float*)d_in[7];
    const float* b2 = (const float*)d_in[8];
    const float* m2 = (const float*)d_in[9];
    const float* v2 = (const float*)d_in[10];
    const float* gp = (const float*)d_in[11];
    const float* bp = (const float*)d_in[12];
    const float* mp = (const float*)d_in[13];
    const float* vp = (const float*)d_in[14];
    const float* w_rep1 = (const float*)d_in[15];
    const float* w_rep2 = (const float*)d_in[16];
    const float* g3 = (const float*)d_in[17];
    const float* b3 = (const float*)d_in[18];
    const float* m3 = (const float*)d_in[19];
    const float* v3 = (const float*)d_in[20];
    float* out = (float*)d_out;

    prep_small<<<1, 512>>>(g1, b1, m1, v1, g2, b2, m2, v2, gp, bp, mp, vp, w_dw2);
    prep_w1<<<MED, C_>>>(w_pw1, g1, v1);
    prep_w2<<<C_, MED>>>(w_rep1, gp, vp);
    prep_rep<<<C_, 256>>>(w_rep1, w_rep2, g3, b3, m3, v3);

    lif1_kernel<<<(int)(STRIDE_T_C / 256), 256>>>(x);

    gemm1_kernel<<<dim3(HW / 128, MED / 128, IMGS), 256>>>();   // (8,4,64)

    mid_kernel<<<B_ * MED, 256>>>();                            // 8192 blocks

    gemm2_kernel<<<dim3(HW / 128, C_ / 128, IMGS), 256>>>();    // (8,2,64)

    dw3_kernel<<<IMGS * C_, 256>>>(out);                        // 16384 blocks
}

// round 5
// speedup vs baseline: 1.9378x; 1.2537x over previous
#include <cuda_runtime.h>
#include <cuda_fp16.h>
#include <cstdint>

#define EPS 1e-5f

// Problem dims
constexpr int T_   = 4;
constexpr int B_   = 16;
constexpr int C_   = 256;
constexpr int MED  = 512;
constexpr int HW   = 1024;   // 32*32
constexpr int IMGS = 64;     // T*B

constexpr size_t N_X  = (size_t)T_ * B_ * C_  * HW;  // 16,777,216
constexpr size_t N_Y1 = (size_t)T_ * B_ * MED * HW;  // 33,554,432
constexpr size_t STRIDE_T_C = (size_t)B_ * C_  * HW;
constexpr size_t STRIDE_T_M = (size_t)B_ * MED * HW;

constexpr float LO_SCALE   = 2048.0f;          // 2^11
constexpr float LO_INV     = 1.0f / 2048.0f;

// ---------------- scratch (device globals) ---------------------------------
__device__ unsigned char g_s1[N_X];     // stage1 spikes  [T,B,C,HW]
__device__ float         g_y1[N_Y1];    // stage1 output  [T,B,MED,HW]
__device__ unsigned char g_s3[N_Y1];    // stage3 spikes  [T,B,MED,HW]
__device__ float         g_zv[N_X];     // stage3 1x1 conv variable part

__device__ __half g_W1hi[MED * C_];
__device__ __half g_W1lo[MED * C_];     // (w-hi)*2^11
__device__ __half g_W2hi[C_ * MED];
__device__ __half g_W2lo[C_ * MED];
__device__ float g_bias1[MED];          // b1 - m1*inv1
__device__ float g_wdw2f[MED * 9];      // w_dw2 * inv2(c)
__device__ float g_c2[MED];             // b2 - m2*inv2
__device__ float g_cp[MED];             // bp - mp*invp
__device__ float g_wr2f[C_ * 9];        // w_rep2 * inv3(o)
__device__ float g_Bt[C_];              // total bias for final dw+BN3

// ---------------- prep kernels ---------------------------------------------
__global__ void prep_small(const float* __restrict__ g1, const float* __restrict__ b1,
                           const float* __restrict__ m1, const float* __restrict__ v1,
                           const float* __restrict__ g2, const float* __restrict__ b2,
                           const float* __restrict__ m2, const float* __restrict__ v2,
                           const float* __restrict__ gp, const float* __restrict__ bp,
                           const float* __restrict__ mp, const float* __restrict__ vp,
                           const float* __restrict__ w_dw2)
{
    int i = threadIdx.x;  // 512
    float inv1 = g1[i] / sqrtf(v1[i] + EPS);
    g_bias1[i] = b1[i] - m1[i] * inv1;

    float inv2 = g2[i] / sqrtf(v2[i] + EPS);
    g_c2[i] = b2[i] - m2[i] * inv2;
#pragma unroll
    for (int j = 0; j < 9; j++) g_wdw2f[i * 9 + j] = w_dw2[i * 9 + j] * inv2;

    float invp = gp[i] / sqrtf(vp[i] + EPS);
    g_cp[i] = bp[i] - mp[i] * invp;
}

__device__ __forceinline__ void split2h(float w, __half& hi, __half& lo)
{
    hi = __float2half_rn(w);
    float r = w - __half2float(hi);
    lo = __float2half_rn(r * LO_SCALE);
}

__global__ void prep_w1(const float* __restrict__ w_pw1,
                        const float* __restrict__ g1, const float* __restrict__ v1)
{
    int o = blockIdx.x;        // 512
    int k = threadIdx.x;       // 256
    float inv1 = g1[o] / sqrtf(v1[o] + EPS);
    float w = w_pw1[o * C_ + k] * inv1;
    __half hi, lo;
    split2h(w, hi, lo);
    g_W1hi[o * C_ + k] = hi;
    g_W1lo[o * C_ + k] = lo;
}

__global__ void prep_w2(const float* __restrict__ w_rep1,
                        const float* __restrict__ gp, const float* __restrict__ vp)
{
    int o = blockIdx.x;        // 256
    int k = threadIdx.x;       // 512
    float invp = gp[k] / sqrtf(vp[k] + EPS);
    float w = w_rep1[o * MED + k] * invp;
    __half hi, lo;
    split2h(w, hi, lo);
    g_W2hi[o * MED + k] = hi;
    g_W2lo[o * MED + k] = lo;
}

// One block per output channel o; parallel reduction over k.
__global__ void prep_rep(const float* __restrict__ w_rep1, const float* __restrict__ w_rep2,
                         const float* __restrict__ g3, const float* __restrict__ b3,
                         const float* __restrict__ m3, const float* __restrict__ v3)
{
    int o = blockIdx.x;        // 256
    int tid = threadIdx.x;     // 256
    float p = w_rep1[o * MED + tid] * g_cp[tid]
            + w_rep1[o * MED + 256 + tid] * g_cp[256 + tid];
    __shared__ float red[256];
    red[tid] = p;
    __syncthreads();
    for (int s = 128; s > 0; s >>= 1) {
        if (tid < s) red[tid] += red[tid + s];
        __syncthreads();
    }
    if (tid == 0) {
        float cb = red[0];
        float inv3 = g3[o] / sqrtf(v3[o] + EPS);
        float sw = 0.f;
#pragma unroll
        for (int j = 0; j < 9; j++) {
            float wv = w_rep2[o * 9 + j];
            g_wr2f[o * 9 + j] = wv * inv3;
            sw += wv;
        }
        g_Bt[o] = (b3[o] - m3[o] * inv3) + inv3 * cb * sw;
    }
}

// ---------------- stage 1 LIF -----------------------------------------------
__device__ __forceinline__ float quant01(float m) {
    return rintf(fminf(fmaxf(m, 0.f), 1.f));
}

__global__ void lif1_kernel(const float* __restrict__ x)
{
    size_t idx = (size_t)blockIdx.x * blockDim.x + threadIdx.x;
    float mem = 0.f, sp = 0.f;
#pragma unroll
    for (int t = 0; t < T_; t++) {
        float v = x[(size_t)t * STRIDE_T_C + idx];
        mem = (mem - sp * 0.5f) * 0.25f + v;
        sp  = quant01(mem);
        g_s1[(size_t)t * STRIDE_T_C + idx] = (unsigned char)sp;
    }
}

// ---------------- fp16 tensor-core spike GEMM (2-way split, dual acc) -------
// C[img][M,1024] = (Ahi + Alo*2^-11)[M,K] * spikes[img][K,1024] (+bias)
// hi pass -> accA ; lo pass -> accB (own scale). Combine in fp32 epilogue.
// Block tile 128x128x32, 8 warps in 2(m)x4(n), warp tile 64x32.

#define LDA_PAD 40   // 32 + 8 fp16 pad -> conflict-free ldmatrix
#define LDB_PAD 136  // 128 + 8

__device__ __forceinline__ void ldmx4(uint32_t& r0, uint32_t& r1, uint32_t& r2, uint32_t& r3,
                                      const __half* p)
{
    uint32_t a = (uint32_t)__cvta_generic_to_shared(p);
    asm volatile("ldmatrix.sync.aligned.m8n8.x4.shared.b16 {%0,%1,%2,%3}, [%4];"
                 : "=r"(r0), "=r"(r1), "=r"(r2), "=r"(r3) : "r"(a));
}

__device__ __forceinline__ void ldmx2t(uint32_t& r0, uint32_t& r1, const __half* p)
{
    uint32_t a = (uint32_t)__cvta_generic_to_shared(p);
    asm volatile("ldmatrix.sync.aligned.m8n8.x2.trans.shared.b16 {%0,%1}, [%2];"
                 : "=r"(r0), "=r"(r1) : "r"(a));
}

__device__ __forceinline__ void mma16816h(float* c, uint32_t a0, uint32_t a1, uint32_t a2,
                                          uint32_t a3, uint32_t b0, uint32_t b1)
{
    asm volatile(
        "mma.sync.aligned.m16n8k16.row.col.f32.f16.f16.f32 "
        "{%0,%1,%2,%3}, {%4,%5,%6,%7}, {%8,%9}, {%0,%1,%2,%3};"
        : "+f"(c[0]), "+f"(c[1]), "+f"(c[2]), "+f"(c[3])
        : "r"(a0), "r"(a1), "r"(a2), "r"(a3), "r"(b0), "r"(b1));
}

template <int M, int K, bool BIAS>
__device__ __forceinline__ void gemm_tc_body(const __half* __restrict__ Ahi,
                                             const __half* __restrict__ Alo,
                                             const unsigned char* __restrict__ Bspk,
                                             float* __restrict__ Cout,
                                             const float* __restrict__ bias)
{
    int img = blockIdx.z;
    const unsigned char* Bp = Bspk + (size_t)img * K * HW;
    float* Cp = Cout + (size_t)img * M * HW;
    int m0 = blockIdx.y * 128;
    int n0 = blockIdx.x * 128;

    __shared__ __align__(16) __half Ahs[128 * LDA_PAD];
    __shared__ __align__(16) __half Als[128 * LDA_PAD];
    __shared__ __align__(16) __half Bs[32 * LDB_PAD];

    int tid  = threadIdx.x;
    int warp = tid >> 5, lane = tid & 31;
    int warp_m = (warp & 1) * 64;   // 2 warps along M
    int warp_n = (warp >> 1) * 32;  // 4 warps along N

    float accA[4][4][4];   // hi pass
    float accB[4][4][4];   // lo pass (scaled by 2^11)
#pragma unroll
    for (int i = 0; i < 4; i++)
#pragma unroll
        for (int j = 0; j < 4; j++)
#pragma unroll
            for (int q = 0; q < 4; q++) { accA[i][j][q] = 0.f; accB[i][j][q] = 0.f; }

    int arow = tid >> 1;              // 0..127
    int acol = (tid & 1) * 16;
    int brow = tid >> 3;              // 0..31
    int bcol = (tid & 7) * 16;

    for (int kc = 0; kc < K; kc += 32) {
        // ---- A hi/lo: 128 x 32 fp16 each ----
        {
            const uint4* s0 = (const uint4*)(Ahi + (size_t)(m0 + arow) * K + kc + acol);
            uint4 v0 = s0[0], v1 = s0[1];
            *(uint4*)&Ahs[arow * LDA_PAD + acol]     = v0;
            *(uint4*)&Ahs[arow * LDA_PAD + acol + 8] = v1;
            const uint4* s2 = (const uint4*)(Alo + (size_t)(m0 + arow) * K + kc + acol);
            uint4 w0 = s2[0], w1 = s2[1];
            *(uint4*)&Als[arow * LDA_PAD + acol]     = w0;
            *(uint4*)&Als[arow * LDA_PAD + acol + 8] = w1;
        }
        // ---- B: 32 x 128 uint8 -> fp16 (1.0f16 = 0x3C00) ----
        {
            uint4 raw = *(const uint4*)(Bp + (size_t)(kc + brow) * HW + n0 + bcol);
            uint32_t out[8];
            uint32_t ws[4] = {raw.x, raw.y, raw.z, raw.w};
#pragma unroll
            for (int q = 0; q < 4; q++) {
                uint32_t w = ws[q];
                out[q * 2 + 0] = ((w)       & 1u) * 0x3C00u | ((w >> 8)  & 1u) * 0x3C000000u;
                out[q * 2 + 1] = ((w >> 16) & 1u) * 0x3C00u | ((w >> 24) & 1u) * 0x3C000000u;
            }
            uint4* dst = (uint4*)&Bs[brow * LDB_PAD + bcol];
            dst[0] = make_uint4(out[0], out[1], out[2], out[3]);
            dst[1] = make_uint4(out[4], out[5], out[6], out[7]);
        }
        __syncthreads();

#pragma unroll
        for (int ks = 0; ks < 2; ks++) {
            int koff = ks * 16;
            uint32_t bf[4][2];
#pragma unroll
            for (int ni = 0; ni < 4; ni++) {
                const __half* p = &Bs[(koff + (lane & 15)) * LDB_PAD + warp_n + ni * 8];
                ldmx2t(bf[ni][0], bf[ni][1], p);
            }
#pragma unroll
            for (int mi = 0; mi < 4; mi++) {
                int row = warp_m + mi * 16 + (lane & 15);
                int col = koff + (lane >> 4) * 8;
                uint32_t a0, a1, a2, a3;
                ldmx4(a0, a1, a2, a3, &Ahs[row * LDA_PAD + col]);
#pragma unroll
                for (int ni = 0; ni < 4; ni++)
                    mma16816h(accA[mi][ni], a0, a1, a2, a3, bf[ni][0], bf[ni][1]);
                ldmx4(a0, a1, a2, a3, &Als[row * LDA_PAD + col]);
#pragma unroll
                for (int ni = 0; ni < 4; ni++)
                    mma16816h(accB[mi][ni], a0, a1, a2, a3, bf[ni][0], bf[ni][1]);
            }
        }
        __syncthreads();
    }

    // ---- epilogue: IEEE fp32 combine, lo scaled back by 2^-11 ----
#pragma unroll
    for (int mi = 0; mi < 4; mi++) {
        int r0 = m0 + warp_m + mi * 16 + (lane >> 2);
        int r1 = r0 + 8;
        float b0 = BIAS ? bias[r0] : 0.f;
        float b1 = BIAS ? bias[r1] : 0.f;
#pragma unroll
        for (int ni = 0; ni < 4; ni++) {
            int c = n0 + warp_n + ni * 8 + (lane & 3) * 2;
            float2 v0 = make_float2(fmaf(accB[mi][ni][0], LO_INV, accA[mi][ni][0]) + b0,
                                    fmaf(accB[mi][ni][1], LO_INV, accA[mi][ni][1]) + b0);
            float2 v1 = make_float2(fmaf(accB[mi][ni][2], LO_INV, accA[mi][ni][2]) + b1,
                                    fmaf(accB[mi][ni][3], LO_INV, accA[mi][ni][3]) + b1);
            *(float2*)(Cp + (size_t)r0 * HW + c) = v0;
            *(float2*)(Cp + (size_t)r1 * HW + c) = v1;
        }
    }
}

__global__ void __launch_bounds__(256) gemm1_kernel()
{
    gemm_tc_body<MED, C_, true>(g_W1hi, g_W1lo, g_s1, g_y1, g_bias1);
}

__global__ void __launch_bounds__(256) gemm2_kernel()
{
    gemm_tc_body<C_, MED, false>(g_W2hi, g_W2lo, g_s3, g_zv, nullptr);
}

// ---------------- fused LIF2 + dw3x3+BN2 + LIF3 ----------------------------
__global__ void __launch_bounds__(256) mid_kernel()
{
    int bx = blockIdx.x;          // 16*512
    int b  = bx >> 9;
    int c  = bx & 511;
    size_t chanbase = ((size_t)b * MED + c) * HW;

    __shared__ float tile[HW];

    float wreg[9];
#pragma unroll
    for (int j = 0; j < 9; j++) wreg[j] = g_wdw2f[c * 9 + j];
    float cc = g_c2[c];

    int tid = threadIdx.x;
    float mem2[4] = {0, 0, 0, 0}, sp2[4] = {0, 0, 0, 0};
    float mem3[4] = {0, 0, 0, 0}, sp3[4] = {0, 0, 0, 0};

#pragma unroll
    for (int t = 0; t < T_; t++) {
        size_t base = (size_t)t * STRIDE_T_M + chanbase;
#pragma unroll
        for (int i = 0; i < 4; i++) {
            int p = tid + i * 256;
            float v = g_y1[base + p];
            mem2[i] = (mem2[i] - sp2[i] * 0.5f) * 0.25f + v;
            sp2[i]  = quant01(mem2[i]);
            tile[p] = sp2[i];
        }
        __syncthreads();
#pragma unroll
        for (int i = 0; i < 4; i++) {
            int p = tid + i * 256;
            int h = p >> 5, wcol = p & 31;
            float conv = 0.f;
#pragma unroll
            for (int ky = 0; ky < 3; ky++) {
                int hh = h + ky - 1;
                if ((unsigned)hh < 32u) {
#pragma unroll
                    for (int kx = 0; kx < 3; kx++) {
                        int ww = wcol + kx - 1;
                        if ((unsigned)ww < 32u)
                            conv = fmaf(wreg[ky * 3 + kx], tile[hh * 32 + ww], conv);
                    }
                }
            }
            float y2v = conv + cc;
            mem3[i] = (mem3[i] - sp3[i] * 0.5f) * 0.25f + y2v;
            sp3[i]  = quant01(mem3[i]);
            g_s3[base + p] = (unsigned char)sp3[i];
        }
        __syncthreads();
    }
}

// ---------------- final dw3x3 (+folded BN3 + pad-ring bias) ----------------
__global__ void __launch_bounds__(256) dw3_kernel(float* __restrict__ out)
{
    int plane = blockIdx.x;        // 64*256
    int o = plane & 255;
    size_t base = (size_t)plane * HW;

    __shared__ float tile[HW];

    float wreg[9];
#pragma unroll
    for (int j = 0; j < 9; j++) wreg[j] = g_wr2f[o * 9 + j];
    float bt = g_Bt[o];

    int tid = threadIdx.x;
#pragma unroll
    for (int i = 0; i < 4; i++) {
        int p = tid + i * 256;
        tile[p] = g_zv[base + p];
    }
    __syncthreads();
#pragma unroll
    for (int i = 0; i < 4; i++) {
        int p = tid + i * 256;
        int h = p >> 5, wcol = p & 31;
        float conv = 0.f;
#pragma unroll
        for (int ky = 0; ky < 3; ky++) {
            int hh = h + ky - 1;
            if ((unsigned)hh < 32u) {
#pragma unroll
                for (int kx = 0; kx < 3; kx++) {
                    int ww = wcol + kx - 1;
                    if ((unsigned)ww < 32u)
                        conv = fmaf(wreg[ky * 3 + kx], tile[hh * 32 + ww], conv);
                }
            }
        }
        out[base + p] = conv + bt;
    }
}

// ---------------- launch ---------------------------------------------------
extern "C" void kernel_launch(void* const* d_in, const int* in_sizes, int n_in,
                              void* d_out, int out_size)
{
    const float* x      = (const float*)d_in[0];
    const float* w_pw1  = (const float*)d_in[1];
    const float* g1 = (const float*)d_in[2];
    const float* b1 = (const float*)d_in[3];
    const float* m1 = (const float*)d_in[4];
    const float* v1 = (const float*)d_in[5];
    const float* w_dw2  = (const float*)d_in[6];
    const float* g2 = (const float*)d_in[7];
    const float* b2 = (const float*)d_in[8];
    const float* m2 = (const float*)d_in[9];
    const float* v2 = (const float*)d_in[10];
    const float* gp = (const float*)d_in[11];
    const float* bp = (const float*)d_in[12];
    const float* mp = (const float*)d_in[13];
    const float* vp = (const float*)d_in[14];
    const float* w_rep1 = (const float*)d_in[15];
    const float* w_rep2 = (const float*)d_in[16];
    const float* g3 = (const float*)d_in[17];
    const float* b3 = (const float*)d_in[18];
    const float* m3 = (const float*)d_in[19];
    const float* v3 = (const float*)d_in[20];
    float* out = (float*)d_out;

    prep_small<<<1, 512>>>(g1, b1, m1, v1, g2, b2, m2, v2, gp, bp, mp, vp, w_dw2);
    prep_w1<<<MED, C_>>>(w_pw1, g1, v1);
    prep_w2<<<C_, MED>>>(w_rep1, gp, vp);
    prep_rep<<<C_, 256>>>(w_rep1, w_rep2, g3, b3, m3, v3);

    lif1_kernel<<<(int)(STRIDE_T_C / 256), 256>>>(x);

    gemm1_kernel<<<dim3(HW / 128, MED / 128, IMGS), 256>>>();   // (8,4,64)

    mid_kernel<<<B_ * MED, 256>>>();                            // 8192 blocks

    gemm2_kernel<<<dim3(HW / 128, C_ / 128, IMGS), 256>>>();    // (8,2,64)

    dw3_kernel<<<IMGS * C_, 256>>>(out);                        // 16384 blocks
}

// round 6
// speedup vs baseline: 2.2396x; 1.1557x over previous
#include <cuda_runtime.h>
#include <cuda_fp16.h>
#include <cstdint>

#define EPS 1e-5f

// Problem dims
constexpr int T_   = 4;
constexpr int B_   = 16;
constexpr int C_   = 256;
constexpr int MED  = 512;
constexpr int HW   = 1024;   // 32*32
constexpr int IMGS = 64;     // T*B

constexpr size_t N_X  = (size_t)T_ * B_ * C_  * HW;  // 16,777,216
constexpr size_t N_Y1 = (size_t)T_ * B_ * MED * HW;  // 33,554,432
constexpr size_t STRIDE_T_C = (size_t)B_ * C_  * HW;
constexpr size_t STRIDE_T_M = (size_t)B_ * MED * HW;

constexpr float LO_SCALE   = 2048.0f;          // 2^11
constexpr float LO_INV     = 1.0f / 2048.0f;

// ---------------- scratch (device globals) ---------------------------------
__device__ unsigned char g_s1[N_X];     // stage1 spikes  [T,B,C,HW]
__device__ float         g_y1[N_Y1];    // stage1 output  [T,B,MED,HW]
__device__ unsigned char g_s3[N_Y1];    // stage3 spikes  [T,B,MED,HW]
__device__ float         g_zv[N_X];     // stage3 1x1 conv variable part

__device__ __half g_W1hi[MED * C_];
__device__ __half g_W1lo[MED * C_];     // (w-hi)*2^11
__device__ __half g_W2hi[C_ * MED];
__device__ __half g_W2lo[C_ * MED];
__device__ float g_bias1[MED];          // b1 - m1*inv1
__device__ float g_wdw2f[MED * 9];      // w_dw2 * inv2(c)
__device__ float g_c2[MED];             // b2 - m2*inv2
__device__ float g_cp[MED];             // bp - mp*invp
__device__ float g_wr2f[C_ * 9];        // w_rep2 * inv3(o)
__device__ float g_Bt[C_];              // total bias for final dw+BN3

// ---------------- prep kernels ---------------------------------------------
__global__ void prep_small(const float* __restrict__ g1, const float* __restrict__ b1,
                           const float* __restrict__ m1, const float* __restrict__ v1,
                           const float* __restrict__ g2, const float* __restrict__ b2,
                           const float* __restrict__ m2, const float* __restrict__ v2,
                           const float* __restrict__ gp, const float* __restrict__ bp,
                           const float* __restrict__ mp, const float* __restrict__ vp,
                           const float* __restrict__ w_dw2)
{
    int i = threadIdx.x;  // 512
    float inv1 = g1[i] / sqrtf(v1[i] + EPS);
    g_bias1[i] = b1[i] - m1[i] * inv1;

    float inv2 = g2[i] / sqrtf(v2[i] + EPS);
    g_c2[i] = b2[i] - m2[i] * inv2;
#pragma unroll
    for (int j = 0; j < 9; j++) g_wdw2f[i * 9 + j] = w_dw2[i * 9 + j] * inv2;

    float invp = gp[i] / sqrtf(vp[i] + EPS);
    g_cp[i] = bp[i] - mp[i] * invp;
}

__device__ __forceinline__ void split2h(float w, __half& hi, __half& lo)
{
    hi = __float2half_rn(w);
    float r = w - __half2float(hi);
    lo = __float2half_rn(r * LO_SCALE);
}

__global__ void prep_w1(const float* __restrict__ w_pw1,
                        const float* __restrict__ g1, const float* __restrict__ v1)
{
    int o = blockIdx.x;        // 512
    int k = threadIdx.x;       // 256
    float inv1 = g1[o] / sqrtf(v1[o] + EPS);
    float w = w_pw1[o * C_ + k] * inv1;
    __half hi, lo;
    split2h(w, hi, lo);
    g_W1hi[o * C_ + k] = hi;
    g_W1lo[o * C_ + k] = lo;
}

__global__ void prep_w2(const float* __restrict__ w_rep1,
                        const float* __restrict__ gp, const float* __restrict__ vp)
{
    int o = blockIdx.x;        // 256
    int k = threadIdx.x;       // 512
    float invp = gp[k] / sqrtf(vp[k] + EPS);
    float w = w_rep1[o * MED + k] * invp;
    __half hi, lo;
    split2h(w, hi, lo);
    g_W2hi[o * MED + k] = hi;
    g_W2lo[o * MED + k] = lo;
}

// One block per output channel o; parallel reduction over k.
__global__ void prep_rep(const float* __restrict__ w_rep1, const float* __restrict__ w_rep2,
                         const float* __restrict__ g3, const float* __restrict__ b3,
                         const float* __restrict__ m3, const float* __restrict__ v3)
{
    int o = blockIdx.x;        // 256
    int tid = threadIdx.x;     // 256
    float p = w_rep1[o * MED + tid] * g_cp[tid]
            + w_rep1[o * MED + 256 + tid] * g_cp[256 + tid];
    __shared__ float red[256];
    red[tid] = p;
    __syncthreads();
    for (int s = 128; s > 0; s >>= 1) {
        if (tid < s) red[tid] += red[tid + s];
        __syncthreads();
    }
    if (tid == 0) {
        float cb = red[0];
        float inv3 = g3[o] / sqrtf(v3[o] + EPS);
        float sw = 0.f;
#pragma unroll
        for (int j = 0; j < 9; j++) {
            float wv = w_rep2[o * 9 + j];
            g_wr2f[o * 9 + j] = wv * inv3;
            sw += wv;
        }
        g_Bt[o] = (b3[o] - m3[o] * inv3) + inv3 * cb * sw;
    }
}

// ---------------- stage 1 LIF -----------------------------------------------
__device__ __forceinline__ float quant01(float m) {
    return rintf(fminf(fmaxf(m, 0.f), 1.f));
}

__global__ void lif1_kernel(const float* __restrict__ x)
{
    size_t idx = (size_t)blockIdx.x * blockDim.x + threadIdx.x;
    float mem = 0.f, sp = 0.f;
#pragma unroll
    for (int t = 0; t < T_; t++) {
        float v = x[(size_t)t * STRIDE_T_C + idx];
        mem = (mem - sp * 0.5f) * 0.25f + v;
        sp  = quant01(mem);
        g_s1[(size_t)t * STRIDE_T_C + idx] = (unsigned char)sp;
    }
}

// ---------------- fp16 tensor-core spike GEMM (2-way split, dual acc) -------
// C[img][M,1024] = (Ahi + Alo*2^-11)[M,K] * spikes[img][K,1024] (+bias)
// hi pass -> accA ; lo pass -> accB. Register-prefetch double buffering:
// next chunk's global loads issued before computing the current chunk.
// Block tile 128x128x32, 8 warps in 2(m)x4(n), warp tile 64x32.

#define LDA_PAD 40   // 32 + 8 fp16 pad -> conflict-free ldmatrix
#define LDB_PAD 136  // 128 + 8

__device__ __forceinline__ void ldmx4(uint32_t& r0, uint32_t& r1, uint32_t& r2, uint32_t& r3,
                                      const __half* p)
{
    uint32_t a = (uint32_t)__cvta_generic_to_shared(p);
    asm volatile("ldmatrix.sync.aligned.m8n8.x4.shared.b16 {%0,%1,%2,%3}, [%4];"
                 : "=r"(r0), "=r"(r1), "=r"(r2), "=r"(r3) : "r"(a));
}

__device__ __forceinline__ void ldmx2t(uint32_t& r0, uint32_t& r1, const __half* p)
{
    uint32_t a = (uint32_t)__cvta_generic_to_shared(p);
    asm volatile("ldmatrix.sync.aligned.m8n8.x2.trans.shared.b16 {%0,%1}, [%2];"
                 : "=r"(r0), "=r"(r1) : "r"(a));
}

__device__ __forceinline__ void mma16816h(float* c, uint32_t a0, uint32_t a1, uint32_t a2,
                                          uint32_t a3, uint32_t b0, uint32_t b1)
{
    asm volatile(
        "mma.sync.aligned.m16n8k16.row.col.f32.f16.f16.f32 "
        "{%0,%1,%2,%3}, {%4,%5,%6,%7}, {%8,%9}, {%0,%1,%2,%3};"
        : "+f"(c[0]), "+f"(c[1]), "+f"(c[2]), "+f"(c[3])
        : "r"(a0), "r"(a1), "r"(a2), "r"(a3), "r"(b0), "r"(b1));
}

template <int M, int K, bool BIAS>
__device__ __forceinline__ void gemm_tc_body(const __half* __restrict__ Ahi,
                                             const __half* __restrict__ Alo,
                                             const unsigned char* __restrict__ Bspk,
                                             float* __restrict__ Cout,
                                             const float* __restrict__ bias)
{
    int img = blockIdx.z;
    const unsigned char* Bp = Bspk + (size_t)img * K * HW;
    float* Cp = Cout + (size_t)img * M * HW;
    int m0 = blockIdx.y * 128;
    int n0 = blockIdx.x * 128;

    __shared__ __align__(16) __half Ahs[128 * LDA_PAD];
    __shared__ __align__(16) __half Als[128 * LDA_PAD];
    __shared__ __align__(16) __half Bs[32 * LDB_PAD];

    int tid  = threadIdx.x;
    int warp = tid >> 5, lane = tid & 31;
    int warp_m = (warp & 1) * 64;   // 2 warps along M
    int warp_n = (warp >> 1) * 32;  // 4 warps along N

    float accA[4][4][4];   // hi pass
    float accB[4][4][4];   // lo pass (scaled by 2^11)
#pragma unroll
    for (int i = 0; i < 4; i++)
#pragma unroll
        for (int j = 0; j < 4; j++)
#pragma unroll
            for (int q = 0; q < 4; q++) { accA[i][j][q] = 0.f; accB[i][j][q] = 0.f; }

    int arow = tid >> 1;              // 0..127
    int acol = (tid & 1) * 16;
    int brow = tid >> 3;              // 0..31
    int bcol = (tid & 7) * 16;

    const __half* pAh = Ahi + (size_t)(m0 + arow) * K + acol;
    const __half* pAl = Alo + (size_t)(m0 + arow) * K + acol;
    const unsigned char* pB = Bp + (size_t)brow * HW + n0 + bcol;

    // registers holding the staged chunk
    uint4 rAh0, rAh1, rAl0, rAl1, rB;

    // prologue: global-load chunk 0
    rAh0 = *(const uint4*)(pAh);
    rAh1 = *(const uint4*)(pAh + 8);
    rAl0 = *(const uint4*)(pAl);
    rAl1 = *(const uint4*)(pAl + 8);
    rB   = *(const uint4*)(pB);

    // store chunk 0 to smem
    {
        *(uint4*)&Ahs[arow * LDA_PAD + acol]     = rAh0;
        *(uint4*)&Ahs[arow * LDA_PAD + acol + 8] = rAh1;
        *(uint4*)&Als[arow * LDA_PAD + acol]     = rAl0;
        *(uint4*)&Als[arow * LDA_PAD + acol + 8] = rAl1;
        uint32_t out[8];
        uint32_t ws[4] = {rB.x, rB.y, rB.z, rB.w};
#pragma unroll
        for (int q = 0; q < 4; q++) {
            uint32_t w = ws[q];
            out[q * 2 + 0] = ((w)       & 1u) * 0x3C00u | ((w >> 8)  & 1u) * 0x3C000000u;
            out[q * 2 + 1] = ((w >> 16) & 1u) * 0x3C00u | ((w >> 24) & 1u) * 0x3C000000u;
        }
        uint4* dst = (uint4*)&Bs[brow * LDB_PAD + bcol];
        dst[0] = make_uint4(out[0], out[1], out[2], out[3]);
        dst[1] = make_uint4(out[4], out[5], out[6], out[7]);
    }
    __syncthreads();

    for (int kc = 0; kc < K; kc += 32) {
        bool has_next = (kc + 32 < K);
        // ---- prefetch next chunk into registers (overlaps with compute) ----
        if (has_next) {
            rAh0 = *(const uint4*)(pAh + (kc + 32));
            rAh1 = *(const uint4*)(pAh + (kc + 32) + 8);
            rAl0 = *(const uint4*)(pAl + (kc + 32));
            rAl1 = *(const uint4*)(pAl + (kc + 32) + 8);
            rB   = *(const uint4*)(pB + (size_t)(kc + 32) * HW);
        }

        // ---- compute current chunk from smem ----
#pragma unroll
        for (int ks = 0; ks < 2; ks++) {
            int koff = ks * 16;
            uint32_t bf[4][2];
#pragma unroll
            for (int ni = 0; ni < 4; ni++) {
                const __half* p = &Bs[(koff + (lane & 15)) * LDB_PAD + warp_n + ni * 8];
                ldmx2t(bf[ni][0], bf[ni][1], p);
            }
#pragma unroll
            for (int mi = 0; mi < 4; mi++) {
                int row = warp_m + mi * 16 + (lane & 15);
                int col = koff + (lane >> 4) * 8;
                uint32_t a0, a1, a2, a3;
                ldmx4(a0, a1, a2, a3, &Ahs[row * LDA_PAD + col]);
#pragma unroll
                for (int ni = 0; ni < 4; ni++)
                    mma16816h(accA[mi][ni], a0, a1, a2, a3, bf[ni][0], bf[ni][1]);
                ldmx4(a0, a1, a2, a3, &Als[row * LDA_PAD + col]);
#pragma unroll
                for (int ni = 0; ni < 4; ni++)
                    mma16816h(accB[mi][ni], a0, a1, a2, a3, bf[ni][0], bf[ni][1]);
            }
        }

        if (has_next) {
            __syncthreads();   // all warps done reading smem for this chunk
            // ---- store prefetched chunk to smem ----
            *(uint4*)&Ahs[arow * LDA_PAD + acol]     = rAh0;
            *(uint4*)&Ahs[arow * LDA_PAD + acol + 8] = rAh1;
            *(uint4*)&Als[arow * LDA_PAD + acol]     = rAl0;
            *(uint4*)&Als[arow * LDA_PAD + acol + 8] = rAl1;
            uint32_t out[8];
            uint32_t ws[4] = {rB.x, rB.y, rB.z, rB.w};
#pragma unroll
            for (int q = 0; q < 4; q++) {
                uint32_t w = ws[q];
                out[q * 2 + 0] = ((w)       & 1u) * 0x3C00u | ((w >> 8)  & 1u) * 0x3C000000u;
                out[q * 2 + 1] = ((w >> 16) & 1u) * 0x3C00u | ((w >> 24) & 1u) * 0x3C000000u;
            }
            uint4* dst = (uint4*)&Bs[brow * LDB_PAD + bcol];
            dst[0] = make_uint4(out[0], out[1], out[2], out[3]);
            dst[1] = make_uint4(out[4], out[5], out[6], out[7]);
            __syncthreads();
        }
    }

    // ---- epilogue: IEEE fp32 combine, lo scaled back by 2^-11 ----
#pragma unroll
    for (int mi = 0; mi < 4; mi++) {
        int r0 = m0 + warp_m + mi * 16 + (lane >> 2);
        int r1 = r0 + 8;
        float b0 = BIAS ? bias[r0] : 0.f;
        float b1 = BIAS ? bias[r1] : 0.f;
#pragma unroll
        for (int ni = 0; ni < 4; ni++) {
            int c = n0 + warp_n + ni * 8 + (lane & 3) * 2;
            float2 v0 = make_float2(fmaf(accB[mi][ni][0], LO_INV, accA[mi][ni][0]) + b0,
                                    fmaf(accB[mi][ni][1], LO_INV, accA[mi][ni][1]) + b0);
            float2 v1 = make_float2(fmaf(accB[mi][ni][2], LO_INV, accA[mi][ni][2]) + b1,
                                    fmaf(accB[mi][ni][3], LO_INV, accA[mi][ni][3]) + b1);
            *(float2*)(Cp + (size_t)r0 * HW + c) = v0;
            *(float2*)(Cp + (size_t)r1 * HW + c) = v1;
        }
    }
}

__global__ void __launch_bounds__(256) gemm1_kernel()
{
    gemm_tc_body<MED, C_, true>(g_W1hi, g_W1lo, g_s1, g_y1, g_bias1);
}

__global__ void __launch_bounds__(256) gemm2_kernel()
{
    gemm_tc_body<C_, MED, false>(g_W2hi, g_W2lo, g_s3, g_zv, nullptr);
}

// ---------------- fused LIF2 + dw3x3+BN2 + LIF3 ----------------------------
__global__ void __launch_bounds__(256) mid_kernel()
{
    int bx = blockIdx.x;          // 16*512
    int b  = bx >> 9;
    int c  = bx & 511;
    size_t chanbase = ((size_t)b * MED + c) * HW;

    __shared__ float tile[HW];

    float wreg[9];
#pragma unroll
    for (int j = 0; j < 9; j++) wreg[j] = g_wdw2f[c * 9 + j];
    float cc = g_c2[c];

    int tid = threadIdx.x;
    float mem2[4] = {0, 0, 0, 0}, sp2[4] = {0, 0, 0, 0};
    float mem3[4] = {0, 0, 0, 0}, sp3[4] = {0, 0, 0, 0};

#pragma unroll
    for (int t = 0; t < T_; t++) {
        size_t base = (size_t)t * STRIDE_T_M + chanbase;
#pragma unroll
        for (int i = 0; i < 4; i++) {
            int p = tid + i * 256;
            float v = g_y1[base + p];
            mem2[i] = (mem2[i] - sp2[i] * 0.5f) * 0.25f + v;
            sp2[i]  = quant01(mem2[i]);
            tile[p] = sp2[i];
        }
        __syncthreads();
#pragma unroll
        for (int i = 0; i < 4; i++) {
            int p = tid + i * 256;
            int h = p >> 5, wcol = p & 31;
            float conv = 0.f;
#pragma unroll
            for (int ky = 0; ky < 3; ky++) {
                int hh = h + ky - 1;
                if ((unsigned)hh < 32u) {
#pragma unroll
                    for (int kx = 0; kx < 3; kx++) {
                        int ww = wcol + kx - 1;
                        if ((unsigned)ww < 32u)
                            conv = fmaf(wreg[ky * 3 + kx], tile[hh * 32 + ww], conv);
                    }
                }
            }
            float y2v = conv + cc;
            mem3[i] = (mem3[i] - sp3[i] * 0.5f) * 0.25f + y2v;
            sp3[i]  = quant01(mem3[i]);
            g_s3[base + p] = (unsigned char)sp3[i];
        }
        __syncthreads();
    }
}

// ---------------- final dw3x3 (+folded BN3 + pad-ring bias) ----------------
__global__ void __launch_bounds__(256) dw3_kernel(float* __restrict__ out)
{
    int plane = blockIdx.x;        // 64*256
    int o = plane & 255;
    size_t base = (size_t)plane * HW;

    __shared__ float tile[HW];

    float wreg[9];
#pragma unroll
    for (int j = 0; j < 9; j++) wreg[j] = g_wr2f[o * 9 + j];
    float bt = g_Bt[o];

    int tid = threadIdx.x;
#pragma unroll
    for (int i = 0; i < 4; i++) {
        int p = tid + i * 256;
        tile[p] = g_zv[base + p];
    }
    __syncthreads();
#pragma unroll
    for (int i = 0; i < 4; i++) {
        int p = tid + i * 256;
        int h = p >> 5, wcol = p & 31;
        float conv = 0.f;
#pragma unroll
        for (int ky = 0; ky < 3; ky++) {
            int hh = h + ky - 1;
            if ((unsigned)hh < 32u) {
#pragma unroll
                for (int kx = 0; kx < 3; kx++) {
                    int ww = wcol + kx - 1;
                    if ((unsigned)ww < 32u)
                        conv = fmaf(wreg[ky * 3 + kx], tile[hh * 32 + ww], conv);
                }
            }
        }
        out[base + p] = conv + bt;
    }
}

// ---------------- launch ---------------------------------------------------
extern "C" void kernel_launch(void* const* d_in, const int* in_sizes, int n_in,
                              void* d_out, int out_size)
{
    const float* x      = (const float*)d_in[0];
    const float* w_pw1  = (const float*)d_in[1];
    const float* g1 = (const float*)d_in[2];
    const float* b1 = (const float*)d_in[3];
    const float* m1 = (const float*)d_in[4];
    const float* v1 = (const float*)d_in[5];
    const float* w_dw2  = (const float*)d_in[6];
    const float* g2 = (const float*)d_in[7];
    const float* b2 = (const float*)d_in[8];
    const float* m2 = (const float*)d_in[9];
    const float* v2 = (const float*)d_in[10];
    const float* gp = (const float*)d_in[11];
    const float* bp = (const float*)d_in[12];
    const float* mp = (const float*)d_in[13];
    const float* vp = (const float*)d_in[14];
    const float* w_rep1 = (const float*)d_in[15];
    const float* w_rep2 = (const float*)d_in[16];
    const float* g3 = (const float*)d_in[17];
    const float* b3 = (const float*)d_in[18];
    const float* m3 = (const float*)d_in[19];
    const float* v3 = (const float*)d_in[20];
    float* out = (float*)d_out;

    prep_small<<<1, 512>>>(g1, b1, m1, v1, g2, b2, m2, v2, gp, bp, mp, vp, w_dw2);
    prep_w1<<<MED, C_>>>(w_pw1, g1, v1);
    prep_w2<<<C_, MED>>>(w_rep1, gp, vp);
    prep_rep<<<C_, 256>>>(w_rep1, w_rep2, g3, b3, m3, v3);

    lif1_kernel<<<(int)(STRIDE_T_C / 256), 256>>>(x);

    gemm1_kernel<<<dim3(HW / 128, MED / 128, IMGS), 256>>>();   // (8,4,64)

    mid_kernel<<<B_ * MED, 256>>>();                            // 8192 blocks

    gemm2_kernel<<<dim3(HW / 128, C_ / 128, IMGS), 256>>>();    // (8,2,64)

    dw3_kernel<<<IMGS * C_, 256>>>(out);                        // 16384 blocks
}

// round 7
// speedup vs baseline: 2.6319x; 1.1752x over previous
#include <cuda_runtime.h>
#include <cuda_fp16.h>
#include <cstdint>

#define EPS 1e-5f

// Problem dims
constexpr int T_   = 4;
constexpr int B_   = 16;
constexpr int C_   = 256;
constexpr int MED  = 512;
constexpr int HW   = 1024;   // 32*32
constexpr int IMGS = 64;     // T*B

constexpr size_t N_X  = (size_t)T_ * B_ * C_  * HW;  // 16,777,216
constexpr size_t N_Y1 = (size_t)T_ * B_ * MED * HW;  // 33,554,432
constexpr size_t STRIDE_T_C = (size_t)B_ * C_  * HW;
constexpr size_t STRIDE_T_M = (size_t)B_ * MED * HW;

constexpr float LO_SCALE   = 2048.0f;          // 2^11
constexpr float LO_INV     = 1.0f / 2048.0f;

// ---------------- scratch (device globals) ---------------------------------
__device__ unsigned char g_s1[N_X];     // stage1 spikes  [T,B,C,HW]
__device__ float         g_y1[N_Y1];    // stage1 output  [T,B,MED,HW]
__device__ unsigned char g_s3[N_Y1];    // stage3 spikes  [T,B,MED,HW]
__device__ float         g_zv[N_X];     // stage3 1x1 conv variable part

__device__ __half g_W1hi[MED * C_];
__device__ __half g_W1lo[MED * C_];     // (w-hi)*2^11
__device__ __half g_W2hi[C_ * MED];     // single-pass fp16 (no threshold downstream)
__device__ float g_bias1[MED];          // b1 - m1*inv1
__device__ float g_wdw2f[MED * 9];      // w_dw2 * inv2(c)
__device__ float g_c2[MED];             // b2 - m2*inv2
__device__ float g_cp[MED];             // bp - mp*invp
__device__ float g_wr2f[C_ * 9];        // w_rep2 * inv3(o)
__device__ float g_Bt[C_];              // total bias for final dw+BN3

// ---------------- prep kernels ---------------------------------------------
__global__ void prep_small(const float* __restrict__ g1, const float* __restrict__ b1,
                           const float* __restrict__ m1, const float* __restrict__ v1,
                           const float* __restrict__ g2, const float* __restrict__ b2,
                           const float* __restrict__ m2, const float* __restrict__ v2,
                           const float* __restrict__ gp, const float* __restrict__ bp,
                           const float* __restrict__ mp, const float* __restrict__ vp,
                           const float* __restrict__ w_dw2)
{
    int i = threadIdx.x;  // 512
    float inv1 = g1[i] / sqrtf(v1[i] + EPS);
    g_bias1[i] = b1[i] - m1[i] * inv1;

    float inv2 = g2[i] / sqrtf(v2[i] + EPS);
    g_c2[i] = b2[i] - m2[i] * inv2;
#pragma unroll
    for (int j = 0; j < 9; j++) g_wdw2f[i * 9 + j] = w_dw2[i * 9 + j] * inv2;

    float invp = gp[i] / sqrtf(vp[i] + EPS);
    g_cp[i] = bp[i] - mp[i] * invp;
}

__device__ __forceinline__ void split2h(float w, __half& hi, __half& lo)
{
    hi = __float2half_rn(w);
    float r = w - __half2float(hi);
    lo = __float2half_rn(r * LO_SCALE);
}

__global__ void prep_w1(const float* __restrict__ w_pw1,
                        const float* __restrict__ g1, const float* __restrict__ v1)
{
    int o = blockIdx.x;        // 512
    int k = threadIdx.x;       // 256
    float inv1 = g1[o] / sqrtf(v1[o] + EPS);
    float w = w_pw1[o * C_ + k] * inv1;
    __half hi, lo;
    split2h(w, hi, lo);
    g_W1hi[o * C_ + k] = hi;
    g_W1lo[o * C_ + k] = lo;
}

__global__ void prep_w2(const float* __restrict__ w_rep1,
                        const float* __restrict__ gp, const float* __restrict__ vp)
{
    int o = blockIdx.x;        // 256
    int k = threadIdx.x;       // 512
    float invp = gp[k] / sqrtf(vp[k] + EPS);
    float w = w_rep1[o * MED + k] * invp;
    g_W2hi[o * MED + k] = __float2half_rn(w);
}

// One block per output channel o; parallel reduction over k.
__global__ void prep_rep(const float* __restrict__ w_rep1, const float* __restrict__ w_rep2,
                         const float* __restrict__ g3, const float* __restrict__ b3,
                         const float* __restrict__ m3, const float* __restrict__ v3)
{
    int o = blockIdx.x;        // 256
    int tid = threadIdx.x;     // 256
    float p = w_rep1[o * MED + tid] * g_cp[tid]
            + w_rep1[o * MED + 256 + tid] * g_cp[256 + tid];
    __shared__ float red[256];
    red[tid] = p;
    __syncthreads();
    for (int s = 128; s > 0; s >>= 1) {
        if (tid < s) red[tid] += red[tid + s];
        __syncthreads();
    }
    if (tid == 0) {
        float cb = red[0];
        float inv3 = g3[o] / sqrtf(v3[o] + EPS);
        float sw = 0.f;
#pragma unroll
        for (int j = 0; j < 9; j++) {
            float wv = w_rep2[o * 9 + j];
            g_wr2f[o * 9 + j] = wv * inv3;
            sw += wv;
        }
        g_Bt[o] = (b3[o] - m3[o] * inv3) + inv3 * cb * sw;
    }
}

// ---------------- stage 1 LIF -----------------------------------------------
__device__ __forceinline__ float quant01(float m) {
    return rintf(fminf(fmaxf(m, 0.f), 1.f));
}

__global__ void lif1_kernel(const float* __restrict__ x)
{
    size_t idx = (size_t)blockIdx.x * blockDim.x + threadIdx.x;
    float mem = 0.f, sp = 0.f;
#pragma unroll
    for (int t = 0; t < T_; t++) {
        float v = x[(size_t)t * STRIDE_T_C + idx];
        mem = (mem - sp * 0.5f) * 0.25f + v;
        sp  = quant01(mem);
        g_s1[(size_t)t * STRIDE_T_C + idx] = (unsigned char)sp;
    }
}

// ---------------- fp16 tensor-core spike GEMM -------------------------------
// TWO=true : C = (Ahi + Alo*2^-11) * spikes  (dual accumulators, fp32-exact W)
// TWO=false: C = Ahi * spikes                (single pass; no threshold after)
// Register-prefetch double buffering; block 128x128x32; 8 warps 2(m)x4(n).

#define LDA_PAD 40   // 32 + 8 fp16 pad -> conflict-free ldmatrix
#define LDB_PAD 136  // 128 + 8

__device__ __forceinline__ void ldmx4(uint32_t& r0, uint32_t& r1, uint32_t& r2, uint32_t& r3,
                                      const __half* p)
{
    uint32_t a = (uint32_t)__cvta_generic_to_shared(p);
    asm volatile("ldmatrix.sync.aligned.m8n8.x4.shared.b16 {%0,%1,%2,%3}, [%4];"
                 : "=r"(r0), "=r"(r1), "=r"(r2), "=r"(r3) : "r"(a));
}

__device__ __forceinline__ void ldmx2t(uint32_t& r0, uint32_t& r1, const __half* p)
{
    uint32_t a = (uint32_t)__cvta_generic_to_shared(p);
    asm volatile("ldmatrix.sync.aligned.m8n8.x2.trans.shared.b16 {%0,%1}, [%2];"
                 : "=r"(r0), "=r"(r1) : "r"(a));
}

__device__ __forceinline__ void mma16816h(float* c, uint32_t a0, uint32_t a1, uint32_t a2,
                                          uint32_t a3, uint32_t b0, uint32_t b1)
{
    asm volatile(
        "mma.sync.aligned.m16n8k16.row.col.f32.f16.f16.f32 "
        "{%0,%1,%2,%3}, {%4,%5,%6,%7}, {%8,%9}, {%0,%1,%2,%3};"
        : "+f"(c[0]), "+f"(c[1]), "+f"(c[2]), "+f"(c[3])
        : "r"(a0), "r"(a1), "r"(a2), "r"(a3), "r"(b0), "r"(b1));
}

template <int M, int K, bool BIAS, bool TWO>
__device__ __forceinline__ void gemm_tc_body(const __half* __restrict__ Ahi,
                                             const __half* __restrict__ Alo,
                                             const unsigned char* __restrict__ Bspk,
                                             float* __restrict__ Cout,
                                             const float* __restrict__ bias)
{
    int img = blockIdx.z;
    const unsigned char* Bp = Bspk + (size_t)img * K * HW;
    float* Cp = Cout + (size_t)img * M * HW;
    int m0 = blockIdx.y * 128;
    int n0 = blockIdx.x * 128;

    __shared__ __align__(16) __half Ahs[128 * LDA_PAD];
    __shared__ __align__(16) __half Als[TWO ? 128 * LDA_PAD : 8];
    __shared__ __align__(16) __half Bs[32 * LDB_PAD];

    int tid  = threadIdx.x;
    int warp = tid >> 5, lane = tid & 31;
    int warp_m = (warp & 1) * 64;   // 2 warps along M
    int warp_n = (warp >> 1) * 32;  // 4 warps along N

    float accA[4][4][4];
    float accB[TWO ? 4 : 1][4][4];
#pragma unroll
    for (int i = 0; i < 4; i++)
#pragma unroll
        for (int j = 0; j < 4; j++)
#pragma unroll
            for (int q = 0; q < 4; q++) accA[i][j][q] = 0.f;
    if (TWO) {
#pragma unroll
        for (int i = 0; i < 4; i++)
#pragma unroll
            for (int j = 0; j < 4; j++)
#pragma unroll
                for (int q = 0; q < 4; q++) accB[i][j][q] = 0.f;
    }

    int arow = tid >> 1;              // 0..127
    int acol = (tid & 1) * 16;
    int brow = tid >> 3;              // 0..31
    int bcol = (tid & 7) * 16;

    const __half* pAh = Ahi + (size_t)(m0 + arow) * K + acol;
    const __half* pAl = TWO ? (Alo + (size_t)(m0 + arow) * K + acol) : nullptr;
    const unsigned char* pB = Bp + (size_t)brow * HW + n0 + bcol;

    uint4 rAh0, rAh1, rAl0 = {}, rAl1 = {}, rB;

    // prologue: global-load chunk 0
    rAh0 = *(const uint4*)(pAh);
    rAh1 = *(const uint4*)(pAh + 8);
    if (TWO) {
        rAl0 = *(const uint4*)(pAl);
        rAl1 = *(const uint4*)(pAl + 8);
    }
    rB   = *(const uint4*)(pB);

    // store chunk 0 to smem
    {
        *(uint4*)&Ahs[arow * LDA_PAD + acol]     = rAh0;
        *(uint4*)&Ahs[arow * LDA_PAD + acol + 8] = rAh1;
        if (TWO) {
            *(uint4*)&Als[arow * LDA_PAD + acol]     = rAl0;
            *(uint4*)&Als[arow * LDA_PAD + acol + 8] = rAl1;
        }
        uint32_t out[8];
        uint32_t ws[4] = {rB.x, rB.y, rB.z, rB.w};
#pragma unroll
        for (int q = 0; q < 4; q++) {
            uint32_t w = ws[q];
            out[q * 2 + 0] = ((w)       & 1u) * 0x3C00u | ((w >> 8)  & 1u) * 0x3C000000u;
            out[q * 2 + 1] = ((w >> 16) & 1u) * 0x3C00u | ((w >> 24) & 1u) * 0x3C000000u;
        }
        uint4* dst = (uint4*)&Bs[brow * LDB_PAD + bcol];
        dst[0] = make_uint4(out[0], out[1], out[2], out[3]);
        dst[1] = make_uint4(out[4], out[5], out[6], out[7]);
    }
    __syncthreads();

    for (int kc = 0; kc < K; kc += 32) {
        bool has_next = (kc + 32 < K);
        if (has_next) {
            rAh0 = *(const uint4*)(pAh + (kc + 32));
            rAh1 = *(const uint4*)(pAh + (kc + 32) + 8);
            if (TWO) {
                rAl0 = *(const uint4*)(pAl + (kc + 32));
                rAl1 = *(const uint4*)(pAl + (kc + 32) + 8);
            }
            rB   = *(const uint4*)(pB + (size_t)(kc + 32) * HW);
        }

#pragma unroll
        for (int ks = 0; ks < 2; ks++) {
            int koff = ks * 16;
            uint32_t bf[4][2];
#pragma unroll
            for (int ni = 0; ni < 4; ni++) {
                const __half* p = &Bs[(koff + (lane & 15)) * LDB_PAD + warp_n + ni * 8];
                ldmx2t(bf[ni][0], bf[ni][1], p);
            }
#pragma unroll
            for (int mi = 0; mi < 4; mi++) {
                int row = warp_m + mi * 16 + (lane & 15);
                int col = koff + (lane >> 4) * 8;
                uint32_t a0, a1, a2, a3;
                ldmx4(a0, a1, a2, a3, &Ahs[row * LDA_PAD + col]);
#pragma unroll
                for (int ni = 0; ni < 4; ni++)
                    mma16816h(accA[mi][ni], a0, a1, a2, a3, bf[ni][0], bf[ni][1]);
                if (TWO) {
                    ldmx4(a0, a1, a2, a3, &Als[row * LDA_PAD + col]);
#pragma unroll
                    for (int ni = 0; ni < 4; ni++)
                        mma16816h(accB[mi][ni], a0, a1, a2, a3, bf[ni][0], bf[ni][1]);
                }
            }
        }

        if (has_next) {
            __syncthreads();
            *(uint4*)&Ahs[arow * LDA_PAD + acol]     = rAh0;
            *(uint4*)&Ahs[arow * LDA_PAD + acol + 8] = rAh1;
            if (TWO) {
                *(uint4*)&Als[arow * LDA_PAD + acol]     = rAl0;
                *(uint4*)&Als[arow * LDA_PAD + acol + 8] = rAl1;
            }
            uint32_t out[8];
            uint32_t ws[4] = {rB.x, rB.y, rB.z, rB.w};
#pragma unroll
            for (int q = 0; q < 4; q++) {
                uint32_t w = ws[q];
                out[q * 2 + 0] = ((w)       & 1u) * 0x3C00u | ((w >> 8)  & 1u) * 0x3C000000u;
                out[q * 2 + 1] = ((w >> 16) & 1u) * 0x3C00u | ((w >> 24) & 1u) * 0x3C000000u;
            }
            uint4* dst = (uint4*)&Bs[brow * LDB_PAD + bcol];
            dst[0] = make_uint4(out[0], out[1], out[2], out[3]);
            dst[1] = make_uint4(out[4], out[5], out[6], out[7]);
            __syncthreads();
        }
    }

    // ---- epilogue ----
#pragma unroll
    for (int mi = 0; mi < 4; mi++) {
        int r0 = m0 + warp_m + mi * 16 + (lane >> 2);
        int r1 = r0 + 8;
        float b0 = BIAS ? bias[r0] : 0.f;
        float b1 = BIAS ? bias[r1] : 0.f;
        float o0, o1, o2, o3;
        if (TWO) {
            o0 = fmaf(accB[mi][0][0], LO_INV, accA[mi][0][0]);  // placeholder, done per ni below
        }
#pragma unroll
        for (int ni = 0; ni < 4; ni++) {
            int c = n0 + warp_n + ni * 8 + (lane & 3) * 2;
            if (TWO) {
                o0 = fmaf(accB[mi][ni][0], LO_INV, accA[mi][ni][0]) + b0;
                o1 = fmaf(accB[mi][ni][1], LO_INV, accA[mi][ni][1]) + b0;
                o2 = fmaf(accB[mi][ni][2], LO_INV, accA[mi][ni][2]) + b1;
                o3 = fmaf(accB[mi][ni][3], LO_INV, accA[mi][ni][3]) + b1;
            } else {
                o0 = accA[mi][ni][0] + b0;
                o1 = accA[mi][ni][1] + b0;
                o2 = accA[mi][ni][2] + b1;
                o3 = accA[mi][ni][3] + b1;
            }
            *(float2*)(Cp + (size_t)r0 * HW + c) = make_float2(o0, o1);
            *(float2*)(Cp + (size_t)r1 * HW + c) = make_float2(o2, o3);
        }
    }
}

__global__ void __launch_bounds__(256) gemm1_kernel()
{
    gemm_tc_body<MED, C_, true, true>(g_W1hi, g_W1lo, g_s1, g_y1, g_bias1);
}

__global__ void __launch_bounds__(256) gemm2_kernel()
{
    gemm_tc_body<C_, MED, false, false>(g_W2hi, nullptr, g_s3, g_zv, nullptr);
}

// ---------------- fused LIF2 + dw3x3+BN2 + LIF3 ----------------------------
__global__ void __launch_bounds__(256) mid_kernel()
{
    int bx = blockIdx.x;          // 16*512
    int b  = bx >> 9;
    int c  = bx & 511;
    size_t chanbase = ((size_t)b * MED + c) * HW;

    __shared__ float tile[HW];

    float wreg[9];
#pragma unroll
    for (int j = 0; j < 9; j++) wreg[j] = g_wdw2f[c * 9 + j];
    float cc = g_c2[c];

    int tid = threadIdx.x;
    float mem2[4] = {0, 0, 0, 0}, sp2[4] = {0, 0, 0, 0};
    float mem3[4] = {0, 0, 0, 0}, sp3[4] = {0, 0, 0, 0};

#pragma unroll
    for (int t = 0; t < T_; t++) {
        size_t base = (size_t)t * STRIDE_T_M + chanbase;
#pragma unroll
        for (int i = 0; i < 4; i++) {
            int p = tid + i * 256;
            float v = g_y1[base + p];
            mem2[i] = (mem2[i] - sp2[i] * 0.5f) * 0.25f + v;
            sp2[i]  = quant01(mem2[i]);
            tile[p] = sp2[i];
        }
        __syncthreads();
#pragma unroll
        for (int i = 0; i < 4; i++) {
            int p = tid + i * 256;
            int h = p >> 5, wcol = p & 31;
            float conv = 0.f;
#pragma unroll
            for (int ky = 0; ky < 3; ky++) {
                int hh = h + ky - 1;
                if ((unsigned)hh < 32u) {
#pragma unroll
                    for (int kx = 0; kx < 3; kx++) {
                        int ww = wcol + kx - 1;
                        if ((unsigned)ww < 32u)
                            conv = fmaf(wreg[ky * 3 + kx], tile[hh * 32 + ww], conv);
                    }
                }
            }
            float y2v = conv + cc;
            mem3[i] = (mem3[i] - sp3[i] * 0.5f) * 0.25f + y2v;
            sp3[i]  = quant01(mem3[i]);
            g_s3[base + p] = (unsigned char)sp3[i];
        }
        __syncthreads();
    }
}

// ---------------- final dw3x3 (+folded BN3 + pad-ring bias) ----------------
__global__ void __launch_bounds__(256) dw3_kernel(float* __restrict__ out)
{
    int plane = blockIdx.x;        // 64*256
    int o = plane & 255;
    size_t base = (size_t)plane * HW;

    __shared__ float tile[HW];

    float wreg[9];
#pragma unroll
    for (int j = 0; j < 9; j++) wreg[j] = g_wr2f[o * 9 + j];
    float bt = g_Bt[o];

    int tid = threadIdx.x;
#pragma unroll
    for (int i = 0; i < 4; i++) {
        int p = tid + i * 256;
        tile[p] = g_zv[base + p];
    }
    __syncthreads();
#pragma unroll
    for (int i = 0; i < 4; i++) {
        int p = tid + i * 256;
        int h = p >> 5, wcol = p & 31;
        float conv = 0.f;
#pragma unroll
        for (int ky = 0; ky < 3; ky++) {
            int hh = h + ky - 1;
            if ((unsigned)hh < 32u) {
#pragma unroll
                for (int kx = 0; kx < 3; kx++) {
                    int ww = wcol + kx - 1;
                    if ((unsigned)ww < 32u)
                        conv = fmaf(wreg[ky * 3 + kx], tile[hh * 32 + ww], conv);
                }
            }
        }
        out[base + p] = conv + bt;
    }
}

// ---------------- launch ---------------------------------------------------
extern "C" void kernel_launch(void* const* d_in, const int* in_sizes, int n_in,
                              void* d_out, int out_size)
{
    const float* x      = (const float*)d_in[0];
    const float* w_pw1  = (const float*)d_in[1];
    const float* g1 = (const float*)d_in[2];
    const float* b1 = (const float*)d_in[3];
    const float* m1 = (const float*)d_in[4];
    const float* v1 = (const float*)d_in[5];
    const float* w_dw2  = (const float*)d_in[6];
    const float* g2 = (const float*)d_in[7];
    const float* b2 = (const float*)d_in[8];
    const float* m2 = (const float*)d_in[9];
    const float* v2 = (const float*)d_in[10];
    const float* gp = (const float*)d_in[11];
    const float* bp = (const float*)d_in[12];
    const float* mp = (const float*)d_in[13];
    const float* vp = (const float*)d_in[14];
    const float* w_rep1 = (const float*)d_in[15];
    const float* w_rep2 = (const float*)d_in[16];
    const float* g3 = (const float*)d_in[17];
    const float* b3 = (const float*)d_in[18];
    const float* m3 = (const float*)d_in[19];
    const float* v3 = (const float*)d_in[20];
    float* out = (float*)d_out;

    prep_small<<<1, 512>>>(g1, b1, m1, v1, g2, b2, m2, v2, gp, bp, mp, vp, w_dw2);
    prep_w1<<<MED, C_>>>(w_pw1, g1, v1);
    prep_w2<<<C_, MED>>>(w_rep1, gp, vp);
    prep_rep<<<C_, 256>>>(w_rep1, w_rep2, g3, b3, m3, v3);

    lif1_kernel<<<(int)(STRIDE_T_C / 256), 256>>>(x);

    gemm1_kernel<<<dim3(HW / 128, MED / 128, IMGS), 256>>>();   // (8,4,64)

    mid_kernel<<<B_ * MED, 256>>>();                            // 8192 blocks

    gemm2_kernel<<<dim3(HW / 128, C_ / 128, IMGS), 256>>>();    // (8,2,64)

    dw3_kernel<<<IMGS * C_, 256>>>(out);                        // 16384 blocks
}